// round 2
// baseline (speedup 1.0000x reference)
#include <cuda_runtime.h>
#include <cstdint>

#define Bb   64
#define Tt   1024
#define Ee   512
#define Vv   256

typedef unsigned long long u64;

// ---------------- device scratch ----------------
__device__ float    g_P[Vv * Ee];                 // P[v][o] = emb[v]·w_x[o] + b_cell[o]
__device__ float    g_hs[(size_t)Tt * Bb * Ee];   // hs[t][b][e]  (128 MB)
__device__ unsigned g_flag[128 * 32];             // per-CTA step flag, 128B stride

// ---------------- packed f32x2 helpers ----------------
__device__ __forceinline__ u64 fma2(u64 a, u64 b, u64 c) {
    u64 d;
    asm("fma.rn.f32x2 %0, %1, %2, %3;" : "=l"(d) : "l"(a), "l"(b), "l"(c));
    return d;
}
__device__ __forceinline__ float lo32(u64 v) { return __uint_as_float((unsigned)(v & 0xffffffffull)); }
__device__ __forceinline__ float hi32(u64 v) { return __uint_as_float((unsigned)(v >> 32)); }
__device__ __forceinline__ u64 pack2(float a) {
    u64 d; asm("mov.b64 %0, {%1, %1};" : "=l"(d) : "r"(__float_as_uint(a))); return d;
}
__device__ __forceinline__ void st_rel(unsigned* p, unsigned v) {
    asm volatile("st.release.gpu.global.u32 [%0], %1;" :: "l"(p), "r"(v) : "memory");
}
__device__ __forceinline__ unsigned ld_acq(const unsigned* p) {
    unsigned v;
    asm volatile("ld.acquire.gpu.global.u32 %0, [%1];" : "=r"(v) : "l"(p) : "memory");
    return v;
}

// ---------------- flag reset (each replay) ----------------
__global__ void zero_flag_kernel() {
    int i = blockIdx.x * 256 + threadIdx.x;
    if (i < 128 * 32) g_flag[i] = 0u;
}

// ---------------- P = emb @ w_x^T + b_cell   (256 x 512, K=512) ----------------
__global__ void p_gemm_kernel(const float* __restrict__ emb,
                              const float* __restrict__ w_cell,
                              const float* __restrict__ b_cell) {
    __shared__ float As[64][16];
    __shared__ float Bs[16][64];
    int tid = threadIdx.x;
    int rbase = blockIdx.x * 64;   // v
    int cbase = blockIdx.y * 64;   // o
    int ti = tid >> 4, tj = tid & 15;
    int arow = tid >> 2, ac4 = (tid & 3) * 4;
    float acc[4][4] = {};

    for (int k0 = 0; k0 < Ee; k0 += 16) {
        float4 av = *(const float4*)&emb[(rbase + arow) * Ee + k0 + ac4];
        *(float4*)&As[arow][ac4] = av;
        float4 bv = *(const float4*)&w_cell[(size_t)(cbase + arow) * (2 * Ee) + k0 + ac4];
        Bs[ac4 + 0][arow] = bv.x; Bs[ac4 + 1][arow] = bv.y;
        Bs[ac4 + 2][arow] = bv.z; Bs[ac4 + 3][arow] = bv.w;
        __syncthreads();
#pragma unroll
        for (int kk = 0; kk < 16; kk++) {
            float a0 = As[ti * 4 + 0][kk];
            float a1 = As[ti * 4 + 1][kk];
            float a2 = As[ti * 4 + 2][kk];
            float a3 = As[ti * 4 + 3][kk];
            float4 b4 = *(const float4*)&Bs[kk][tj * 4];
            acc[0][0] = fmaf(a0, b4.x, acc[0][0]); acc[0][1] = fmaf(a0, b4.y, acc[0][1]);
            acc[0][2] = fmaf(a0, b4.z, acc[0][2]); acc[0][3] = fmaf(a0, b4.w, acc[0][3]);
            acc[1][0] = fmaf(a1, b4.x, acc[1][0]); acc[1][1] = fmaf(a1, b4.y, acc[1][1]);
            acc[1][2] = fmaf(a1, b4.z, acc[1][2]); acc[1][3] = fmaf(a1, b4.w, acc[1][3]);
            acc[2][0] = fmaf(a2, b4.x, acc[2][0]); acc[2][1] = fmaf(a2, b4.y, acc[2][1]);
            acc[2][2] = fmaf(a2, b4.z, acc[2][2]); acc[2][3] = fmaf(a2, b4.w, acc[2][3]);
            acc[3][0] = fmaf(a3, b4.x, acc[3][0]); acc[3][1] = fmaf(a3, b4.y, acc[3][1]);
            acc[3][2] = fmaf(a3, b4.z, acc[3][2]); acc[3][3] = fmaf(a3, b4.w, acc[3][3]);
        }
        __syncthreads();
    }
#pragma unroll
    for (int ii = 0; ii < 4; ii++) {
        int r = rbase + ti * 4 + ii;
        int c = cbase + tj * 4;
        float4 o;
        o.x = acc[ii][0] + b_cell[c + 0];
        o.y = acc[ii][1] + b_cell[c + 1];
        o.z = acc[ii][2] + b_cell[c + 2];
        o.w = acc[ii][3] + b_cell[c + 3];
        *(float4*)&g_P[r * Ee + c] = o;
    }
}

// ---------------- persistent recurrence kernel ----------------
// 128 CTAs = 8 batch-groups (8 rows) x 16 col-tiles (32 cols).
// Sync is per-batch-group (16 CTAs) via release/acquire flags.
__global__ void __launch_bounds__(256, 1)
rnn_rec_kernel(const int* __restrict__ x,
               const float* __restrict__ w_cell,
               const float* __restrict__ h0) {
    __shared__ __align__(16) float hsm[8 * Ee];     // 16 KB
    __shared__ float psum[8 * 8 * 32];              // 8 KB  [b][ks][c]

    int tid = threadIdx.x;
    int bid = blockIdx.x;
    int io = bid & 15, ib = bid >> 4;
    int obase = io * 32, bbase = ib * 8;
    int c  = tid & 31;       // output col within tile
    int ks = tid >> 5;       // k-slice 0..7 (64 k each)
    int k0 = ks * 64;

    // preload w_h slice: w_h[o][e] = w_cell[o*1024 + 512 + e]  -> 32 u64
    u64 wreg[32];
    {
        const u64* wp = (const u64*)w_cell;
        int base = ((obase + c) * (2 * Ee) + Ee + k0) >> 1;
#pragma unroll
        for (int j = 0; j < 32; j++) wreg[j] = wp[base + j];
    }

    unsigned* myflag = &g_flag[bid * 32];
    unsigned* grpflags = &g_flag[(ib * 16) * 32];
    const int* xrow = x + (bbase + ks) * Tt;     // reduce-phase batch = ks index
    const float* prow_base = g_P + obase;

    for (int t = 0; t < Tt; t++) {
        // ---- load previous h tile (8 x 512 fp32 = 16 KB) ----
        if (t == 0) {
            const float4* h04 = (const float4*)h0;
#pragma unroll
            for (int q = 0; q < 4; q++) {
                int idx = tid + q * 256;
                ((float4*)hsm)[idx] = h04[idx & 127];
            }
        } else {
            const float4* hp4 = (const float4*)(g_hs + ((size_t)(t - 1) * Bb + bbase) * Ee);
#pragma unroll
            for (int q = 0; q < 4; q++) {
                int idx = tid + q * 256;
                ((float4*)hsm)[idx] = __ldcg(&hp4[idx]);
            }
        }
        __syncthreads();

        // ---- partial dots: thread = (col c, k-slice ks), loop over 8 batches ----
#pragma unroll 1
        for (int b = 0; b < 8; b++) {
            const ulonglong2* hp2 = (const ulonglong2*)(hsm + b * Ee + k0);
            u64 a0 = 0ull, a1 = 0ull, a2 = 0ull, a3 = 0ull;
#pragma unroll
            for (int j = 0; j < 8; j++) {
                ulonglong2 h2a = hp2[2 * j];
                ulonglong2 h2b = hp2[2 * j + 1];
                a0 = fma2(h2a.x, wreg[4 * j + 0], a0);
                a1 = fma2(h2a.y, wreg[4 * j + 1], a1);
                a2 = fma2(h2b.x, wreg[4 * j + 2], a2);
                a3 = fma2(h2b.y, wreg[4 * j + 3], a3);
            }
            float r = (lo32(a0) + hi32(a0)) + (lo32(a1) + hi32(a1))
                    + (lo32(a2) + hi32(a2)) + (lo32(a3) + hi32(a3));
            psum[(b * 8 + ks) * 32 + c] = r;
        }
        __syncthreads();

        // ---- reduce 8 partials, add table entry, tanh, store ----
        {
            int rb = ks;      // batch
            int cc = c;
            float s = 0.f;
#pragma unroll
            for (int q = 0; q < 8; q++) s += psum[(rb * 8 + q) * 32 + cc];
            int xv = __ldg(xrow + t);
            float val = s + __ldg(&prow_base[xv * Ee + cc]);
            g_hs[((size_t)t * Bb + bbase + rb) * Ee + obase + cc] = tanhf(val);
        }

        // ---- batch-group barrier: 16 flags, release/acquire ----
        if (t < Tt - 1) {
            __threadfence();
            __syncthreads();
            if (tid == 0) st_rel(myflag, (unsigned)(t + 1));
            if (tid < 16) {
                while (ld_acq(&grpflags[tid * 32]) <= (unsigned)t) { }
            }
            __syncthreads();
        }
    }
}

// ---------------- head GEMM (f32x2): out[b][t][v] = hs·w_head^T + b_head ----------------
// Block tile 64 rows x 128 cols; thread tile 4 x 8 (as 4 u64 col-pairs).
#define HB_PAD 132
__global__ void __launch_bounds__(256)
head_gemm_kernel(const float* __restrict__ w_head,
                 const float* __restrict__ b_head,
                 float* __restrict__ out) {
    __shared__ float As[64][16];            // [row][k]
    __shared__ float Bs[16][HB_PAD];        // [k][col], padded
    int tid = threadIdx.x;
    int rbase = blockIdx.x * 64;
    int cbase = blockIdx.y * 128;
    int ti = tid >> 4, tj = tid & 15;       // thread rows ti*4.., cols tj*8..
    int arow = tid >> 2, ac4 = (tid & 3) * 4;

    u64 acc[4][4];                           // [row][colpair]
#pragma unroll
    for (int i = 0; i < 4; i++)
#pragma unroll
        for (int j = 0; j < 4; j++) acc[i][j] = 0ull;

    for (int k0 = 0; k0 < Ee; k0 += 16) {
        // As: 64x16
        float4 av = *(const float4*)&g_hs[(size_t)(rbase + arow) * Ee + k0 + ac4];
        *(float4*)&As[arow][ac4] = av;
        // Bs: 128 cols x 16 k, transposed store
#pragma unroll
        for (int l = 0; l < 2; l++) {
            int idx = tid + l * 256;
            int col = idx >> 2;
            int kq  = (idx & 3) * 4;
            float4 bv = *(const float4*)&w_head[(size_t)(cbase + col) * Ee + k0 + kq];
            Bs[kq + 0][col] = bv.x; Bs[kq + 1][col] = bv.y;
            Bs[kq + 2][col] = bv.z; Bs[kq + 3][col] = bv.w;
        }
        __syncthreads();
#pragma unroll
        for (int kk = 0; kk < 16; kk++) {
            u64 a0 = pack2(As[ti * 4 + 0][kk]);
            u64 a1 = pack2(As[ti * 4 + 1][kk]);
            u64 a2 = pack2(As[ti * 4 + 2][kk]);
            u64 a3 = pack2(As[ti * 4 + 3][kk]);
            ulonglong2 bA = *(const ulonglong2*)&Bs[kk][tj * 8];
            ulonglong2 bB = *(const ulonglong2*)&Bs[kk][tj * 8 + 4];
            acc[0][0] = fma2(a0, bA.x, acc[0][0]); acc[0][1] = fma2(a0, bA.y, acc[0][1]);
            acc[0][2] = fma2(a0, bB.x, acc[0][2]); acc[0][3] = fma2(a0, bB.y, acc[0][3]);
            acc[1][0] = fma2(a1, bA.x, acc[1][0]); acc[1][1] = fma2(a1, bA.y, acc[1][1]);
            acc[1][2] = fma2(a1, bB.x, acc[1][2]); acc[1][3] = fma2(a1, bB.y, acc[1][3]);
            acc[2][0] = fma2(a2, bA.x, acc[2][0]); acc[2][1] = fma2(a2, bA.y, acc[2][1]);
            acc[2][2] = fma2(a2, bB.x, acc[2][2]); acc[2][3] = fma2(a2, bB.y, acc[2][3]);
            acc[3][0] = fma2(a3, bA.x, acc[3][0]); acc[3][1] = fma2(a3, bA.y, acc[3][1]);
            acc[3][2] = fma2(a3, bB.x, acc[3][2]); acc[3][3] = fma2(a3, bB.y, acc[3][3]);
        }
        __syncthreads();
    }

#pragma unroll
    for (int ii = 0; ii < 4; ii++) {
        int r  = rbase + ti * 4 + ii;       // r = t*B + b
        int bb = r & (Bb - 1);
        int tt = r >> 6;
        int cc = cbase + tj * 8;
        float o[8];
#pragma unroll
        for (int j = 0; j < 4; j++) {
            o[2 * j + 0] = lo32(acc[ii][j]) + b_head[cc + 2 * j + 0];
            o[2 * j + 1] = hi32(acc[ii][j]) + b_head[cc + 2 * j + 1];
        }
        float* op = &out[(size_t)bb * (Tt * Vv) + (size_t)tt * Vv + cc];
        *(float4*)op       = make_float4(o[0], o[1], o[2], o[3]);
        *(float4*)(op + 4) = make_float4(o[4], o[5], o[6], o[7]);
    }
}

// ---------------- launch ----------------
extern "C" void kernel_launch(void* const* d_in, const int* in_sizes, int n_in,
                              void* d_out, int out_size) {
    const int*   x      = (const int*)  d_in[0];
    const float* emb    = (const float*)d_in[1];
    const float* w_cell = (const float*)d_in[2];
    const float* b_cell = (const float*)d_in[3];
    const float* w_head = (const float*)d_in[4];
    const float* b_head = (const float*)d_in[5];
    const float* h0     = (const float*)d_in[6];
    float* out = (float*)d_out;

    zero_flag_kernel<<<16, 256>>>();
    p_gemm_kernel<<<dim3(Vv / 64, Ee / 64), 256>>>(emb, w_cell, b_cell);
    rnn_rec_kernel<<<128, 256>>>(x, w_cell, h0);
    head_gemm_kernel<<<dim3((Bb * Tt) / 64, Vv / 128), 256>>>(w_head, b_head, out);
}

// round 3
// speedup vs baseline: 1.2153x; 1.2153x over previous
#include <cuda_runtime.h>
#include <cstdint>

#define Bb   64
#define Tt   1024
#define Ee   512
#define Vv   256

typedef unsigned long long u64;

// ---------------- device scratch ----------------
__device__ float    g_P[Vv * Ee];                 // P[v][o] = emb[v]·w_x[o] + b_cell[o]
__device__ float    g_hs[(size_t)Tt * Bb * Ee];   // hs[t][b][e]  (128 MB)
__device__ unsigned g_flag[128 * 32];             // per-CTA step flag, 128B stride

// ---------------- packed f32x2 helpers ----------------
__device__ __forceinline__ u64 fma2(u64 a, u64 b, u64 c) {
    u64 d;
    asm("fma.rn.f32x2 %0, %1, %2, %3;" : "=l"(d) : "l"(a), "l"(b), "l"(c));
    return d;
}
__device__ __forceinline__ float lo32(u64 v) { return __uint_as_float((unsigned)(v & 0xffffffffull)); }
__device__ __forceinline__ float hi32(u64 v) { return __uint_as_float((unsigned)(v >> 32)); }
__device__ __forceinline__ void st_rel(unsigned* p, unsigned v) {
    asm volatile("st.release.gpu.global.u32 [%0], %1;" :: "l"(p), "r"(v) : "memory");
}
__device__ __forceinline__ unsigned ld_acq(const unsigned* p) {
    unsigned v;
    asm volatile("ld.acquire.gpu.global.u32 %0, [%1];" : "=r"(v) : "l"(p) : "memory");
    return v;
}

// ---------------- flag reset (each replay) ----------------
__global__ void zero_flag_kernel() {
    int i = blockIdx.x * 256 + threadIdx.x;
    if (i < 128 * 32) g_flag[i] = 0u;
}

// ---------------- P = emb @ w_x^T + b_cell   (256 x 512, K=512) ----------------
__global__ void p_gemm_kernel(const float* __restrict__ emb,
                              const float* __restrict__ w_cell,
                              const float* __restrict__ b_cell) {
    __shared__ float As[64][16];
    __shared__ float Bs[16][64];
    int tid = threadIdx.x;
    int rbase = blockIdx.x * 64;   // v
    int cbase = blockIdx.y * 64;   // o
    int ti = tid >> 4, tj = tid & 15;
    int arow = tid >> 2, ac4 = (tid & 3) * 4;
    float acc[4][4] = {};

    for (int k0 = 0; k0 < Ee; k0 += 16) {
        float4 av = *(const float4*)&emb[(rbase + arow) * Ee + k0 + ac4];
        *(float4*)&As[arow][ac4] = av;
        float4 bv = *(const float4*)&w_cell[(size_t)(cbase + arow) * (2 * Ee) + k0 + ac4];
        Bs[ac4 + 0][arow] = bv.x; Bs[ac4 + 1][arow] = bv.y;
        Bs[ac4 + 2][arow] = bv.z; Bs[ac4 + 3][arow] = bv.w;
        __syncthreads();
#pragma unroll
        for (int kk = 0; kk < 16; kk++) {
            float a0 = As[ti * 4 + 0][kk];
            float a1 = As[ti * 4 + 1][kk];
            float a2 = As[ti * 4 + 2][kk];
            float a3 = As[ti * 4 + 3][kk];
            float4 b4 = *(const float4*)&Bs[kk][tj * 4];
            acc[0][0] = fmaf(a0, b4.x, acc[0][0]); acc[0][1] = fmaf(a0, b4.y, acc[0][1]);
            acc[0][2] = fmaf(a0, b4.z, acc[0][2]); acc[0][3] = fmaf(a0, b4.w, acc[0][3]);
            acc[1][0] = fmaf(a1, b4.x, acc[1][0]); acc[1][1] = fmaf(a1, b4.y, acc[1][1]);
            acc[1][2] = fmaf(a1, b4.z, acc[1][2]); acc[1][3] = fmaf(a1, b4.w, acc[1][3]);
            acc[2][0] = fmaf(a2, b4.x, acc[2][0]); acc[2][1] = fmaf(a2, b4.y, acc[2][1]);
            acc[2][2] = fmaf(a2, b4.z, acc[2][2]); acc[2][3] = fmaf(a2, b4.w, acc[2][3]);
            acc[3][0] = fmaf(a3, b4.x, acc[3][0]); acc[3][1] = fmaf(a3, b4.y, acc[3][1]);
            acc[3][2] = fmaf(a3, b4.z, acc[3][2]); acc[3][3] = fmaf(a3, b4.w, acc[3][3]);
        }
        __syncthreads();
    }
#pragma unroll
    for (int ii = 0; ii < 4; ii++) {
        int r = rbase + ti * 4 + ii;
        int c = cbase + tj * 4;
        float4 o;
        o.x = acc[ii][0] + b_cell[c + 0];
        o.y = acc[ii][1] + b_cell[c + 1];
        o.z = acc[ii][2] + b_cell[c + 2];
        o.w = acc[ii][3] + b_cell[c + 3];
        *(float4*)&g_P[r * Ee + c] = o;
    }
}

// ---------------- persistent recurrence kernel ----------------
// 128 CTAs = 8 batch-groups (8 rows) x 16 col-tiles (32 cols).
// Per-slice flag-gated loads; release/acquire sync; P-gather prefetch.
__global__ void __launch_bounds__(256, 1)
rnn_rec_kernel(const int* __restrict__ x,
               const float* __restrict__ w_cell,
               const float* __restrict__ h0) {
    __shared__ __align__(16) float hsm[8 * Ee];     // 16 KB
    __shared__ float psum[8 * 8 * 32];              // 8 KB  [b][ks][c]

    int tid = threadIdx.x;
    int bid = blockIdx.x;
    int io = bid & 15, ib = bid >> 4;
    int obase = io * 32, bbase = ib * 8;
    int c  = tid & 31;       // output col within tile
    int ks = tid >> 5;       // k-slice 0..7 (64 k each)
    int k0 = ks * 64;

    // preload w_h slice: w_h[o][e] = w_cell[o*1024 + 512 + e]  -> 32 u64
    u64 wreg[32];
    {
        const u64* wp = (const u64*)w_cell;
        int base = ((obase + c) * (2 * Ee) + Ee + k0) >> 1;
#pragma unroll
        for (int j = 0; j < 32; j++) wreg[j] = wp[base + j];
    }

    unsigned* myflag = &g_flag[bid * 32];
    // this thread's 4 h-loads all come from producer slice (tid&127)>>3
    const unsigned* pollp = &g_flag[(ib * 16 + ((tid & 127) >> 3)) * 32];
    const int* xrow = x + (bbase + ks) * Tt;     // reduce-phase batch = ks
    const float* prow_base = g_P + obase;

    for (int t = 0; t < Tt; t++) {
        // ---- P-table prefetch (h-independent) ----
        int   xv = __ldg(xrow + t);
        float pv = __ldg(&prow_base[xv * Ee + c]);

        // ---- gather previous h tile ----
        if (t == 0) {
            const float4* h04 = (const float4*)h0;
#pragma unroll
            for (int q = 0; q < 4; q++) {
                int idx = tid + q * 256;
                ((float4*)hsm)[idx] = h04[idx & 127];
            }
        } else {
            // wait only for this thread's producer slice, then load
            while (ld_acq(pollp) < (unsigned)t) { }
            const float4* hp4 = (const float4*)(g_hs + ((size_t)(t - 1) * Bb + bbase) * Ee);
#pragma unroll
            for (int q = 0; q < 4; q++) {
                int idx = tid + q * 256;
                ((float4*)hsm)[idx] = __ldcg(&hp4[idx]);
            }
        }
        __syncthreads();

        // ---- partial dots: thread = (col c, k-slice ks), loop over 8 batches ----
#pragma unroll 1
        for (int b = 0; b < 8; b++) {
            const ulonglong2* hp2 = (const ulonglong2*)(hsm + b * Ee + k0);
            u64 a0 = 0ull, a1 = 0ull, a2 = 0ull, a3 = 0ull;
#pragma unroll
            for (int j = 0; j < 8; j++) {
                ulonglong2 h2a = hp2[2 * j];
                ulonglong2 h2b = hp2[2 * j + 1];
                a0 = fma2(h2a.x, wreg[4 * j + 0], a0);
                a1 = fma2(h2a.y, wreg[4 * j + 1], a1);
                a2 = fma2(h2b.x, wreg[4 * j + 2], a2);
                a3 = fma2(h2b.y, wreg[4 * j + 3], a3);
            }
            float r = (lo32(a0) + hi32(a0)) + (lo32(a1) + hi32(a1))
                    + (lo32(a2) + hi32(a2)) + (lo32(a3) + hi32(a3));
            psum[(b * 8 + ks) * 32 + c] = r;
        }
        __syncthreads();

        // ---- reduce 8 partials (batch = ks), add prefetched P, tanh, store ----
        {
            float s = 0.f;
#pragma unroll
            for (int q = 0; q < 8; q++) s += psum[(ks * 8 + q) * 32 + c];
            float val = s + pv;
            g_hs[((size_t)t * Bb + bbase + ks) * Ee + obase + c] = tanhf(val);
        }
        __syncthreads();                 // all h-stores of this CTA done
        if (tid == 0) st_rel(myflag, (unsigned)(t + 1));
    }
}

// ---------------- head GEMM (R1 version): out[b][t][v] = hs·w_head^T + b_head ----------------
__global__ void head_gemm_kernel(const float* __restrict__ w_head,
                                 const float* __restrict__ b_head,
                                 float* __restrict__ out) {
    __shared__ float As[64][16];   // [row][k]   rows r = t*B + b
    __shared__ float Bs[16][64];   // [k][col]
    int tid = threadIdx.x;
    int rbase = blockIdx.x * 64;
    int cbase = blockIdx.y * 64;
    int ti = tid >> 4, tj = tid & 15;
    int arow = tid >> 2, ac4 = (tid & 3) * 4;
    float acc[4][4] = {};

    for (int k0 = 0; k0 < Ee; k0 += 16) {
        float4 av = *(const float4*)&g_hs[(size_t)(rbase + arow) * Ee + k0 + ac4];
        *(float4*)&As[arow][ac4] = av;
        float4 bv = *(const float4*)&w_head[(size_t)(cbase + arow) * Ee + k0 + ac4];
        Bs[ac4 + 0][arow] = bv.x; Bs[ac4 + 1][arow] = bv.y;
        Bs[ac4 + 2][arow] = bv.z; Bs[ac4 + 3][arow] = bv.w;
        __syncthreads();
#pragma unroll
        for (int kk = 0; kk < 16; kk++) {
            float a0 = As[ti * 4 + 0][kk];
            float a1 = As[ti * 4 + 1][kk];
            float a2 = As[ti * 4 + 2][kk];
            float a3 = As[ti * 4 + 3][kk];
            float4 b4 = *(const float4*)&Bs[kk][tj * 4];
            acc[0][0] = fmaf(a0, b4.x, acc[0][0]); acc[0][1] = fmaf(a0, b4.y, acc[0][1]);
            acc[0][2] = fmaf(a0, b4.z, acc[0][2]); acc[0][3] = fmaf(a0, b4.w, acc[0][3]);
            acc[1][0] = fmaf(a1, b4.x, acc[1][0]); acc[1][1] = fmaf(a1, b4.y, acc[1][1]);
            acc[1][2] = fmaf(a1, b4.z, acc[1][2]); acc[1][3] = fmaf(a1, b4.w, acc[1][3]);
            acc[2][0] = fmaf(a2, b4.x, acc[2][0]); acc[2][1] = fmaf(a2, b4.y, acc[2][1]);
            acc[2][2] = fmaf(a2, b4.z, acc[2][2]); acc[2][3] = fmaf(a2, b4.w, acc[2][3]);
            acc[3][0] = fmaf(a3, b4.x, acc[3][0]); acc[3][1] = fmaf(a3, b4.y, acc[3][1]);
            acc[3][2] = fmaf(a3, b4.z, acc[3][2]); acc[3][3] = fmaf(a3, b4.w, acc[3][3]);
        }
        __syncthreads();
    }
#pragma unroll
    for (int ii = 0; ii < 4; ii++) {
        int r  = rbase + ti * 4 + ii;      // r = t*B + b
        int bb = r & (Bb - 1);
        int tt = r >> 6;
        int cc = cbase + tj * 4;
        float4 o;
        o.x = acc[ii][0] + b_head[cc + 0];
        o.y = acc[ii][1] + b_head[cc + 1];
        o.z = acc[ii][2] + b_head[cc + 2];
        o.w = acc[ii][3] + b_head[cc + 3];
        *(float4*)&out[(size_t)bb * (Tt * Vv) + (size_t)tt * Vv + cc] = o;
    }
}

// ---------------- launch ----------------
extern "C" void kernel_launch(void* const* d_in, const int* in_sizes, int n_in,
                              void* d_out, int out_size) {
    const int*   x      = (const int*)  d_in[0];
    const float* emb    = (const float*)d_in[1];
    const float* w_cell = (const float*)d_in[2];
    const float* b_cell = (const float*)d_in[3];
    const float* w_head = (const float*)d_in[4];
    const float* b_head = (const float*)d_in[5];
    const float* h0     = (const float*)d_in[6];
    float* out = (float*)d_out;

    zero_flag_kernel<<<16, 256>>>();
    p_gemm_kernel<<<dim3(Vv / 64, Ee / 64), 256>>>(emb, w_cell, b_cell);
    rnn_rec_kernel<<<128, 256>>>(x, w_cell, h0);
    head_gemm_kernel<<<dim3((Bb * Tt) / 64, Vv / 64), 256>>>(w_head, b_head, out);
}

// round 4
// speedup vs baseline: 1.4855x; 1.2223x over previous
#include <cuda_runtime.h>
#include <cstdint>

#define Bb   64
#define Tt   1024
#define Ee   512
#define Vv   256

typedef unsigned long long u64;

// ---------------- device scratch ----------------
__device__ float    g_P[Vv * Ee];                 // P[v][o] = emb[v]·w_x[o] + b_cell[o]
__device__ float    g_hs[(size_t)Tt * Bb * Ee];   // hs[t][b][e]  (128 MB)
__device__ unsigned g_flag[128 * 32];             // per-CTA step flag, 128B stride

// ---------------- packed f32x2 helpers ----------------
__device__ __forceinline__ u64 fma2(u64 a, u64 b, u64 c) {
    u64 d;
    asm("fma.rn.f32x2 %0, %1, %2, %3;" : "=l"(d) : "l"(a), "l"(b), "l"(c));
    return d;
}
__device__ __forceinline__ float lo32(u64 v) { return __uint_as_float((unsigned)(v & 0xffffffffull)); }
__device__ __forceinline__ float hi32(u64 v) { return __uint_as_float((unsigned)(v >> 32)); }
__device__ __forceinline__ float hsum(u64 v) { return lo32(v) + hi32(v); }
__device__ __forceinline__ u64 pack2(float a) {
    u64 d; asm("mov.b64 %0, {%1, %1};" : "=l"(d) : "r"(__float_as_uint(a))); return d;
}
__device__ __forceinline__ void st_rel(unsigned* p, unsigned v) {
    asm volatile("st.release.gpu.global.u32 [%0], %1;" :: "l"(p), "r"(v) : "memory");
}
__device__ __forceinline__ unsigned ld_rlx(const unsigned* p) {
    unsigned v;
    asm volatile("ld.relaxed.gpu.global.u32 %0, [%1];" : "=r"(v) : "l"(p) : "memory");
    return v;
}
__device__ __forceinline__ void fence_acq() {
    asm volatile("fence.acq_rel.gpu;" ::: "memory");
}

// ---------------- flag reset (each replay) ----------------
__global__ void zero_flag_kernel() {
    int i = blockIdx.x * 256 + threadIdx.x;
    if (i < 128 * 32) g_flag[i] = 0u;
}

// ---------------- P = emb @ w_x^T + b_cell   (256 x 512, K=512) ----------------
__global__ void p_gemm_kernel(const float* __restrict__ emb,
                              const float* __restrict__ w_cell,
                              const float* __restrict__ b_cell) {
    __shared__ float As[64][16];
    __shared__ float Bs[16][64];
    int tid = threadIdx.x;
    int rbase = blockIdx.x * 64;   // v
    int cbase = blockIdx.y * 64;   // o
    int ti = tid >> 4, tj = tid & 15;
    int arow = tid >> 2, ac4 = (tid & 3) * 4;
    float acc[4][4] = {};

    for (int k0 = 0; k0 < Ee; k0 += 16) {
        float4 av = *(const float4*)&emb[(rbase + arow) * Ee + k0 + ac4];
        *(float4*)&As[arow][ac4] = av;
        float4 bv = *(const float4*)&w_cell[(size_t)(cbase + arow) * (2 * Ee) + k0 + ac4];
        Bs[ac4 + 0][arow] = bv.x; Bs[ac4 + 1][arow] = bv.y;
        Bs[ac4 + 2][arow] = bv.z; Bs[ac4 + 3][arow] = bv.w;
        __syncthreads();
#pragma unroll
        for (int kk = 0; kk < 16; kk++) {
            float a0 = As[ti * 4 + 0][kk];
            float a1 = As[ti * 4 + 1][kk];
            float a2 = As[ti * 4 + 2][kk];
            float a3 = As[ti * 4 + 3][kk];
            float4 b4 = *(const float4*)&Bs[kk][tj * 4];
            acc[0][0] = fmaf(a0, b4.x, acc[0][0]); acc[0][1] = fmaf(a0, b4.y, acc[0][1]);
            acc[0][2] = fmaf(a0, b4.z, acc[0][2]); acc[0][3] = fmaf(a0, b4.w, acc[0][3]);
            acc[1][0] = fmaf(a1, b4.x, acc[1][0]); acc[1][1] = fmaf(a1, b4.y, acc[1][1]);
            acc[1][2] = fmaf(a1, b4.z, acc[1][2]); acc[1][3] = fmaf(a1, b4.w, acc[1][3]);
            acc[2][0] = fmaf(a2, b4.x, acc[2][0]); acc[2][1] = fmaf(a2, b4.y, acc[2][1]);
            acc[2][2] = fmaf(a2, b4.z, acc[2][2]); acc[2][3] = fmaf(a2, b4.w, acc[2][3]);
            acc[3][0] = fmaf(a3, b4.x, acc[3][0]); acc[3][1] = fmaf(a3, b4.y, acc[3][1]);
            acc[3][2] = fmaf(a3, b4.z, acc[3][2]); acc[3][3] = fmaf(a3, b4.w, acc[3][3]);
        }
        __syncthreads();
    }
#pragma unroll
    for (int ii = 0; ii < 4; ii++) {
        int r = rbase + ti * 4 + ii;
        int c = cbase + tj * 4;
        float4 o;
        o.x = acc[ii][0] + b_cell[c + 0];
        o.y = acc[ii][1] + b_cell[c + 1];
        o.z = acc[ii][2] + b_cell[c + 2];
        o.w = acc[ii][3] + b_cell[c + 3];
        *(float4*)&g_P[r * Ee + c] = o;
    }
}

// ---------------- persistent recurrence kernel ----------------
// 128 CTAs = 16 batch-groups (4 rows) x 8 col-tiles (64 cols).
// Thread: lane = col pair (l, l+32), warp = k-slice of 64.
// Warp-level flag gating: warp ks waits only on producer CTA ks of its group.
__global__ void __launch_bounds__(256, 1)
rnn_rec_kernel(const int* __restrict__ x,
               const float* __restrict__ w_cell,
               const float* __restrict__ h0) {
    __shared__ __align__(16) float hsm[8 * 256];    // 8 KB: per-warp 4b x 64k
    __shared__ float psum[4 * 8 * 64];              // 8 KB: [b][ks][c]

    int tid = threadIdx.x;
    int bid = blockIdx.x;
    int io  = bid & 7,  grp = bid >> 3;
    int obase = io * 64, bbase = grp * 4;
    int l  = tid & 31;       // lane: cols obase+l, obase+l+32
    int ks = tid >> 5;       // warp = k-slice (64 k)
    int k0 = ks * 64;

    // preload w_h for 2 cols: w_h[o][e] = w_cell[o*1024 + 512 + e]
    u64 wA[32], wB[32];
    {
        const u64* wp = (const u64*)w_cell;
        int baseA = ((obase + l)      * (2 * Ee) + Ee + k0) >> 1;
        int baseB = ((obase + l + 32) * (2 * Ee) + Ee + k0) >> 1;
#pragma unroll
        for (int j = 0; j < 32; j++) wA[j] = wp[baseA + j];
#pragma unroll
        for (int j = 0; j < 32; j++) wB[j] = wp[baseB + j];
    }

    unsigned* myflag = &g_flag[(grp * 8 + io) * 32];
    const unsigned* pollp = &g_flag[(grp * 8 + ks) * 32];   // one producer per warp

    // reduce-phase identity: b = tid>>6 (0..3), c = tid&63
    int rb = tid >> 6, rc = tid & 63;
    const int* xrow = x + (bbase + rb) * Tt;
    const float* prow_base = g_P + obase + rc;

    float* myhsm = hsm + ks * 256;

    for (int t = 0; t < Tt; t++) {
        // ---- P-table prefetch (h-independent) ----
        int   xv = __ldg(xrow + t);
        float pv = __ldg(&prow_base[xv * Ee]);

        // ---- per-warp gather of this warp's k-slice (4 batches x 64 k) ----
        if (t == 0) {
#pragma unroll
            for (int q = 0; q < 2; q++) {
                int idx = l + 32 * q;                 // 0..63
                int kk  = (idx & 15) * 4;
                *(float4*)&myhsm[(idx >> 4) * 64 + kk] = *(const float4*)&h0[k0 + kk];
            }
        } else {
            while (ld_rlx(pollp) < (unsigned)t) { }
            fence_acq();
#pragma unroll
            for (int q = 0; q < 2; q++) {
                int idx = l + 32 * q;
                int bq  = idx >> 4;
                int kk  = (idx & 15) * 4;
                const float4* src = (const float4*)(g_hs +
                    ((size_t)(t - 1) * Bb + bbase + bq) * Ee + k0 + kk);
                *(float4*)&myhsm[bq * 64 + kk] = __ldcg(src);
            }
        }
        __syncwarp();

        // ---- partial dots: 2 cols x 4 batches x 64 k per thread ----
#pragma unroll
        for (int b = 0; b < 4; b++) {
            const ulonglong2* hp2 = (const ulonglong2*)(myhsm + b * 64);
            u64 aA0 = 0ull, aA1 = 0ull, aB0 = 0ull, aB1 = 0ull;
#pragma unroll
            for (int j = 0; j < 8; j++) {
                ulonglong2 h2a = hp2[2 * j];
                ulonglong2 h2b = hp2[2 * j + 1];
                aA0 = fma2(h2a.x, wA[4 * j + 0], aA0);
                aA1 = fma2(h2a.y, wA[4 * j + 1], aA1);
                aA0 = fma2(h2b.x, wA[4 * j + 2], aA0);
                aA1 = fma2(h2b.y, wA[4 * j + 3], aA1);
                aB0 = fma2(h2a.x, wB[4 * j + 0], aB0);
                aB1 = fma2(h2a.y, wB[4 * j + 1], aB1);
                aB0 = fma2(h2b.x, wB[4 * j + 2], aB0);
                aB1 = fma2(h2b.y, wB[4 * j + 3], aB1);
            }
            psum[(b * 8 + ks) * 64 + l]      = hsum(aA0) + hsum(aA1);
            psum[(b * 8 + ks) * 64 + l + 32] = hsum(aB0) + hsum(aB1);
        }
        __syncthreads();

        // ---- reduce 8 k-slices, add P, tanh, store h_t ----
        {
            float s = 0.f;
#pragma unroll
            for (int q = 0; q < 8; q++) s += psum[(rb * 8 + q) * 64 + rc];
            float val = s + pv;
            g_hs[((size_t)t * Bb + bbase + rb) * Ee + obase + rc] = tanhf(val);
        }
        __syncthreads();
        if (tid == 0) st_rel(myflag, (unsigned)(t + 1));
    }
}

// ---------------- head GEMM (f32x2 inner, 64x64 tile) ----------------
__global__ void __launch_bounds__(256)
head_gemm_kernel(const float* __restrict__ w_head,
                 const float* __restrict__ b_head,
                 float* __restrict__ out) {
    __shared__ float As[64][16];   // [row][k]
    __shared__ float Bs[16][64];   // [k][col]
    int tid = threadIdx.x;
    int rbase = blockIdx.x * 64;
    int cbase = blockIdx.y * 64;
    int ti = tid >> 4, tj = tid & 15;
    int arow = tid >> 2, ac4 = (tid & 3) * 4;

    u64 acc[4][2];
#pragma unroll
    for (int i = 0; i < 4; i++) { acc[i][0] = 0ull; acc[i][1] = 0ull; }

    for (int k0 = 0; k0 < Ee; k0 += 16) {
        float4 av = *(const float4*)&g_hs[(size_t)(rbase + arow) * Ee + k0 + ac4];
        *(float4*)&As[arow][ac4] = av;
        float4 bv = *(const float4*)&w_head[(size_t)(cbase + arow) * Ee + k0 + ac4];
        Bs[ac4 + 0][arow] = bv.x; Bs[ac4 + 1][arow] = bv.y;
        Bs[ac4 + 2][arow] = bv.z; Bs[ac4 + 3][arow] = bv.w;
        __syncthreads();
#pragma unroll
        for (int kq = 0; kq < 16; kq += 4) {
            float4 a0 = *(const float4*)&As[ti * 4 + 0][kq];
            float4 a1 = *(const float4*)&As[ti * 4 + 1][kq];
            float4 a2 = *(const float4*)&As[ti * 4 + 2][kq];
            float4 a3 = *(const float4*)&As[ti * 4 + 3][kq];
            ulonglong2 b0 = *(const ulonglong2*)&Bs[kq + 0][tj * 4];
            ulonglong2 b1 = *(const ulonglong2*)&Bs[kq + 1][tj * 4];
            ulonglong2 b2 = *(const ulonglong2*)&Bs[kq + 2][tj * 4];
            ulonglong2 b3 = *(const ulonglong2*)&Bs[kq + 3][tj * 4];

            u64 p;
            p = pack2(a0.x); acc[0][0] = fma2(p, b0.x, acc[0][0]); acc[0][1] = fma2(p, b0.y, acc[0][1]);
            p = pack2(a1.x); acc[1][0] = fma2(p, b0.x, acc[1][0]); acc[1][1] = fma2(p, b0.y, acc[1][1]);
            p = pack2(a2.x); acc[2][0] = fma2(p, b0.x, acc[2][0]); acc[2][1] = fma2(p, b0.y, acc[2][1]);
            p = pack2(a3.x); acc[3][0] = fma2(p, b0.x, acc[3][0]); acc[3][1] = fma2(p, b0.y, acc[3][1]);

            p = pack2(a0.y); acc[0][0] = fma2(p, b1.x, acc[0][0]); acc[0][1] = fma2(p, b1.y, acc[0][1]);
            p = pack2(a1.y); acc[1][0] = fma2(p, b1.x, acc[1][0]); acc[1][1] = fma2(p, b1.y, acc[1][1]);
            p = pack2(a2.y); acc[2][0] = fma2(p, b1.x, acc[2][0]); acc[2][1] = fma2(p, b1.y, acc[2][1]);
            p = pack2(a3.y); acc[3][0] = fma2(p, b1.x, acc[3][0]); acc[3][1] = fma2(p, b1.y, acc[3][1]);

            p = pack2(a0.z); acc[0][0] = fma2(p, b2.x, acc[0][0]); acc[0][1] = fma2(p, b2.y, acc[0][1]);
            p = pack2(a1.z); acc[1][0] = fma2(p, b2.x, acc[1][0]); acc[1][1] = fma2(p, b2.y, acc[1][1]);
            p = pack2(a2.z); acc[2][0] = fma2(p, b2.x, acc[2][0]); acc[2][1] = fma2(p, b2.y, acc[2][1]);
            p = pack2(a3.z); acc[3][0] = fma2(p, b2.x, acc[3][0]); acc[3][1] = fma2(p, b2.y, acc[3][1]);

            p = pack2(a0.w); acc[0][0] = fma2(p, b3.x, acc[0][0]); acc[0][1] = fma2(p, b3.y, acc[0][1]);
            p = pack2(a1.w); acc[1][0] = fma2(p, b3.x, acc[1][0]); acc[1][1] = fma2(p, b3.y, acc[1][1]);
            p = pack2(a2.w); acc[2][0] = fma2(p, b3.x, acc[2][0]); acc[2][1] = fma2(p, b3.y, acc[2][1]);
            p = pack2(a3.w); acc[3][0] = fma2(p, b3.x, acc[3][0]); acc[3][1] = fma2(p, b3.y, acc[3][1]);
        }
        __syncthreads();
    }
#pragma unroll
    for (int ii = 0; ii < 4; ii++) {
        int r  = rbase + ti * 4 + ii;      // r = t*B + b
        int bb = r & (Bb - 1);
        int tt = r >> 6;
        int cc = cbase + tj * 4;
        float4 o;
        o.x = lo32(acc[ii][0]) + b_head[cc + 0];
        o.y = hi32(acc[ii][0]) + b_head[cc + 1];
        o.z = lo32(acc[ii][1]) + b_head[cc + 2];
        o.w = hi32(acc[ii][1]) + b_head[cc + 3];
        *(float4*)&out[(size_t)bb * (Tt * Vv) + (size_t)tt * Vv + cc] = o;
    }
}

// ---------------- launch ----------------
extern "C" void kernel_launch(void* const* d_in, const int* in_sizes, int n_in,
                              void* d_out, int out_size) {
    const int*   x      = (const int*)  d_in[0];
    const float* emb    = (const float*)d_in[1];
    const float* w_cell = (const float*)d_in[2];
    const float* b_cell = (const float*)d_in[3];
    const float* w_head = (const float*)d_in[4];
    const float* b_head = (const float*)d_in[5];
    const float* h0     = (const float*)d_in[6];
    float* out = (float*)d_out;

    zero_flag_kernel<<<16, 256>>>();
    p_gemm_kernel<<<dim3(Vv / 64, Ee / 64), 256>>>(emb, w_cell, b_cell);
    rnn_rec_kernel<<<128, 256>>>(x, w_cell, h0);
    head_gemm_kernel<<<dim3((Bb * Tt) / 64, Vv / 64), 256>>>(w_head, b_head, out);
}